// round 14
// baseline (speedup 1.0000x reference)
#include <cuda_runtime.h>

typedef unsigned long long ull;
#define EPSV 1e-5f
#define SLICE (4 * 64 * 1024)

// ---------------- scratch (device globals) ----------------
__device__ float g_part[16][SLICE];          // split-K(<=16) partial conv outputs
__device__ float g_y[SLICE];                 // combined raw conv output (pre-BN)
__device__ float g_bn_a[64];                 // folded BN scale
__device__ float g_bn_b[64];                 // folded BN shift
__device__ float g_xf[4 * 12 * 1024];        // regressor output (N,T,WH)
__device__ float g_wT[163584];               // transposed weights [ci][tap][co]
__device__ float2 g_red[64][4];              // per-(channel, image) {sum, sumsq}
__device__ int g_cnt[5 * 64];                // last-block counters per layer/channel

// wT layout: L0 [12][9][64] @0 (6912); L1..4 [64][9][64] @6912+l*36864; reg [64][9][16] @154368

__device__ __forceinline__ void fma2(ull& acc, ull x, ull w) {
    asm("fma.rn.f32x2 %0, %1, %2, %0;" : "+l"(acc) : "l"(x), "l"(w));
}
__device__ __forceinline__ ull dup2(float v) {
    union { float2 f; ull u; } t;
    t.f = make_float2(v, v);
    return t.u;
}

// ---------------- weight transpose + counter reset ----------------
__global__ void wtrans_kernel(const float* __restrict__ conv0_w,
                              const float* __restrict__ conv_w,
                              const float* __restrict__ reg_w) {
    int i = blockIdx.x * 256 + threadIdx.x;
    if (i < 320) g_cnt[i] = 0;
    if (i < 6912) {
        int co = i & 63, rest = i >> 6;
        int tap = rest % 9, ci = rest / 9;
        g_wT[i] = conv0_w[co * 108 + ci * 9 + tap];
        return;
    }
    int j = i - 6912;
    if (j >= 0 && j < 147456) {
        int l = j / 36864, k = j % 36864;
        int co = k & 63, rest = k >> 6;
        int tap = rest % 9, ci = rest / 9;
        g_wT[i] = conv_w[(l * 64 + co) * 576 + ci * 9 + tap];
        return;
    }
    int r = i - 154368;
    if (r >= 0 && r < 9216) {
        int co = r & 15, rest = r >> 4;
        int tap = rest % 9, ci = rest / 9;
        g_wT[i] = (co < 12) ? reg_w[co * 576 + ci * 9 + tap] : 0.f;
    }
}

// ---------------- dense-pixel conv, co-split: block = 128 thr = 4 warps x 8co ----------------
// grid: (32 tiles, SPLITK*2): blockIdx.y>>1 = ci-split, blockIdx.y&1 = co half.
// smA: non-duplicated floats [CIQ][6][40], halos [0]/[33] zero; smW: [CIQ][9][32].
template <int CI, bool BN, int SPLITK, bool ACTFIRST>
__global__ __launch_bounds__(128, 6) void convp_kernel(const float* __restrict__ in,
                                                       const float* __restrict__ wT,
                                                       float* __restrict__ part) {
    constexpr int CIQ = CI / SPLITK;
    const int tid = threadIdx.x;
    const int warp = tid >> 5;
    const int lane = tid & 31;
    const int coBase = (blockIdx.y & 1) * 32;
    const int co0 = coBase + warp * 8;
    const int row = lane >> 3;
    const int pc = (lane & 7) * 4;
    const int px0 = blockIdx.x * 128;        // 4 rows x 32 cols
    const int n = px0 >> 10;
    const int r0 = (px0 & 1023) >> 5;
    const int ci0 = (blockIdx.y >> 1) * CIQ;

    __shared__ __align__(16) float smA[CIQ][6][40];
    __shared__ __align__(16) float smW[CIQ][9][32];

    auto stageActs = [&]() {
        if (tid < CIQ * 12) {
            int pair = tid >> 1;
            int ci = pair / 6, rw = pair % 6;
            smA[ci][rw][(tid & 1) ? 33 : 0] = 0.f;
        }
        for (int idx = tid; idx < CIQ * 48; idx += 128) {
            int ci = idx / 48, rem = idx % 48;
            int rw = rem / 8, q = rem % 8;
            int gr = r0 - 1 + rw;
            int cig = ci0 + ci;
            float4 v = make_float4(0.f, 0.f, 0.f, 0.f);
            if ((unsigned)gr < 32u) {
                v = *(const float4*)&in[((n * CI + cig) << 10) + (gr << 5) + q * 4];
                if (BN) {
                    float a = g_bn_a[cig], b = g_bn_b[cig];
                    v.x = fmaxf(fmaf(v.x, a, b), 0.f);
                    v.y = fmaxf(fmaf(v.y, a, b), 0.f);
                    v.z = fmaxf(fmaf(v.z, a, b), 0.f);
                    v.w = fmaxf(fmaf(v.w, a, b), 0.f);
                }
            }
            float* d = &smA[ci][rw][1 + q * 4];
            d[0] = v.x; d[1] = v.y; d[2] = v.z; d[3] = v.w;
        }
    };
    auto stageWeights = [&]() {
        const float4* src = (const float4*)wT;
        float4* dstw = (float4*)&smW[0][0][0];
        for (int idx = tid; idx < CIQ * 72; idx += 128) {
            int ci = idx / 72, rem = idx % 72;
            int tap = rem / 8, q = rem % 8;
            dstw[idx] = src[((ci0 + ci) * 9 + tap) * 16 + (coBase >> 2) + q];
        }
    };

    if (ACTFIRST) {
        stageActs();
        cudaGridDependencySynchronize();
        stageWeights();
    } else {
        stageWeights();
        cudaGridDependencySynchronize();
        stageActs();
    }
    __syncthreads();

    // ---- compute: acc[jp][cp] = co-pair {co0+2cp, co0+2cp+1}, pixel (row, pc+jp) ----
    ull acc[4][4];
#pragma unroll
    for (int a = 0; a < 4; a++)
#pragma unroll
        for (int b = 0; b < 4; b++) acc[a][b] = 0ULL;

#pragma unroll
    for (int ci = 0; ci < CIQ; ci++) {
#pragma unroll
        for (int kh = 0; kh < 3; kh++) {
            const float* ar = &smA[ci][row + kh][pc];
            float4 a03 = *(const float4*)ar;
            float2 a45 = *(const float2*)(ar + 4);
            ull d[6];
            d[0] = dup2(a03.x); d[1] = dup2(a03.y);
            d[2] = dup2(a03.z); d[3] = dup2(a03.w);
            d[4] = dup2(a45.x); d[5] = dup2(a45.y);
#pragma unroll
            for (int kw = 0; kw < 3; kw++) {
                const float* wr = &smW[ci][kh * 3 + kw][warp * 8];
                ulonglong2 w01 = *(const ulonglong2*)wr;
                ulonglong2 w23 = *(const ulonglong2*)(wr + 4);
#pragma unroll
                for (int jp = 0; jp < 4; jp++) {
                    ull xx = d[kw + jp];
                    fma2(acc[jp][0], xx, w01.x);
                    fma2(acc[jp][1], xx, w01.y);
                    fma2(acc[jp][2], xx, w23.x);
                    fma2(acc[jp][3], xx, w23.y);
                }
            }
        }
    }

    // ---- epilogue ----
    union U { ull u; float2 f; };
    float* dst = part + (blockIdx.y >> 1) * SLICE;
#pragma unroll
    for (int cp = 0; cp < 4; cp++) {
#pragma unroll
        for (int h = 0; h < 2; h++) {
            const int co = co0 + cp * 2 + h;
            float4 o;
            { U u; u.u = acc[0][cp]; o.x = h ? u.f.y : u.f.x; }
            { U u; u.u = acc[1][cp]; o.y = h ? u.f.y : u.f.x; }
            { U u; u.u = acc[2][cp]; o.z = h ? u.f.y : u.f.x; }
            { U u; u.u = acc[3][cp]; o.w = h ? u.f.y : u.f.x; }
            *(float4*)&dst[((n * 64 + co) << 10) + ((r0 + row) << 5) + pc] = o;
        }
    }
}

// ---------------- duplicated-pixel staging (regressor conv) ----------------
template <int CI, int CIQ, int ROWS, bool BN, int NT>
__device__ __forceinline__ void stage_input(float2 (*smA)[ROWS + 2][36],
                                            const float* __restrict__ in,
                                            int tid, int n, int r0, int ci0) {
    constexpr int NR = ROWS + 2;
    constexpr int NPAIR = CIQ * NR;
    constexpr int NV = NPAIR * 8;
    if (tid < NPAIR * 2) {
        int pair = tid >> 1;
        int ci = pair / NR, row = pair % NR;
        smA[ci][row][(tid & 1) ? 33 : 0] = make_float2(0.f, 0.f);
    }
    for (int idx = tid; idx < NV; idx += NT) {
        int pair = idx >> 3, q = idx & 7;
        int ci = pair / NR, row = pair % NR;
        int gr = r0 - 1 + row;
        int cig = ci0 + ci;
        float4 v = make_float4(0.f, 0.f, 0.f, 0.f);
        if ((unsigned)gr < 32u) {
            v = *(const float4*)&in[((n * CI + cig) << 10) + (gr << 5) + q * 4];
            if (BN) {
                float a = g_bn_a[cig], b = g_bn_b[cig];
                v.x = fmaxf(fmaf(v.x, a, b), 0.f);
                v.y = fmaxf(fmaf(v.y, a, b), 0.f);
                v.z = fmaxf(fmaf(v.z, a, b), 0.f);
                v.w = fmaxf(fmaf(v.w, a, b), 0.f);
            }
        }
        float2* base = &smA[ci][row][1 + q * 4];
        base[0] = make_float2(v.x, v.x);
        base[1] = make_float2(v.y, v.y);
        base[2] = make_float2(v.z, v.z);
        base[3] = make_float2(v.w, v.w);
    }
}

// ---------------- regressor conv: 4px x 4co per thread ----------------
template <int CI, int CO, int ROWS, bool BN, int STORECO, int SPLITK>
__global__ __launch_bounds__(256, 1) void convr_kernel(const float* __restrict__ in,
                                                       const float* __restrict__ wT,
                                                       float* __restrict__ part) {
    constexpr int TCO = CO / 4;
    constexpr int CIQ = CI / SPLITK;
    const int tid = threadIdx.x;
    const int tco = tid % TCO;
    const int tpx = tid / TCO;
    const int pr = tpx >> 3;
    const int pc = (tpx & 7) * 4;
    const int px0 = blockIdx.x * (ROWS * 32);
    const int n = px0 >> 10;
    const int r0 = (px0 & 1023) >> 5;
    const int ci0 = blockIdx.y * CIQ;

    __shared__ __align__(16) float2 smA[CIQ][ROWS + 2][36];
    __shared__ __align__(16) float smW[CIQ][9][CO];

    {
        const float4* src = (const float4*)(wT + ci0 * 9 * CO);
        float4* dstw = (float4*)&smW[0][0][0];
        for (int idx = tid; idx < CIQ * 9 * CO / 4; idx += 256) dstw[idx] = src[idx];
    }
    cudaGridDependencySynchronize();
    stage_input<CI, CIQ, ROWS, BN, 256>(smA, in, tid, n, r0, ci0);
    __syncthreads();

    ull acc[4][2];
#pragma unroll
    for (int a = 0; a < 4; a++) { acc[a][0] = 0ULL; acc[a][1] = 0ULL; }

#pragma unroll
    for (int ci = 0; ci < CIQ; ci++) {
#pragma unroll
        for (int kh = 0; kh < 3; kh++) {
            ulonglong2 x01 = *(const ulonglong2*)&smA[ci][pr + kh][pc + 0];
            ulonglong2 x23 = *(const ulonglong2*)&smA[ci][pr + kh][pc + 2];
            ulonglong2 x45 = *(const ulonglong2*)&smA[ci][pr + kh][pc + 4];
            ull xp[6];
            xp[0] = x01.x; xp[1] = x01.y;
            xp[2] = x23.x; xp[3] = x23.y;
            xp[4] = x45.x; xp[5] = x45.y;
#pragma unroll
            for (int kw = 0; kw < 3; kw++) {
                ulonglong2 wv = *(const ulonglong2*)&smW[ci][kh * 3 + kw][tco * 4];
#pragma unroll
                for (int jp = 0; jp < 4; jp++) {
                    fma2(acc[jp][0], xp[kw + jp], wv.x);
                    fma2(acc[jp][1], xp[kw + jp], wv.y);
                }
            }
        }
    }

    union U { ull u; float2 f; };
    float vals[4][4];
#pragma unroll
    for (int jp = 0; jp < 4; jp++) {
        U u0, u1; u0.u = acc[jp][0]; u1.u = acc[jp][1];
        vals[jp][0] = u0.f.x; vals[jp][1] = u0.f.y;
        vals[jp][2] = u1.f.x; vals[jp][3] = u1.f.y;
    }
    float* dst = part + blockIdx.y * SLICE;
#pragma unroll
    for (int jc = 0; jc < 4; jc++) {
        int co = tco * 4 + jc;
        if (STORECO == CO || co < STORECO) {
            float4 o = make_float4(vals[0][jc], vals[1][jc], vals[2][jc], vals[3][jc]);
            *(float4*)&dst[((n * STORECO + co) << 10) + ((r0 + pr) << 5) + pc] = o;
        }
    }
}

// ---------------- combine partials -> y, BN stats, last-block folds (a,b) ----------------
template <int NPARTS>
__global__ __launch_bounds__(256) void stats_kernel(const float* __restrict__ gamma,
                                                    const float* __restrict__ beta,
                                                    int layer) {
    cudaGridDependencySynchronize();
    const int b = blockIdx.x;
    const int c = b & 63;
    const int n = b >> 6;
    const int tid = threadIdx.x;
    const int base = ((n * 64 + c) << 10) + tid * 4;

    float4 y = make_float4(0.f, 0.f, 0.f, 0.f);
#pragma unroll
    for (int p = 0; p < NPARTS; p++) {
        float4 v = *(const float4*)&g_part[p][base];
        y.x += v.x; y.y += v.y; y.z += v.z; y.w += v.w;
    }
    *(float4*)&g_y[base] = y;
    float s = y.x + y.y + y.z + y.w;
    float ss = y.x * y.x + y.y * y.y + y.z * y.z + y.w * y.w;

    const int lane = tid & 31, warp = tid >> 5;
#pragma unroll
    for (int o = 16; o > 0; o >>= 1) {
        s += __shfl_xor_sync(0xffffffffu, s, o);
        ss += __shfl_xor_sync(0xffffffffu, ss, o);
    }
    __shared__ float shs[8], shq[8];
    if (lane == 0) { shs[warp] = s; shq[warp] = ss; }
    __syncthreads();
    if (tid == 0) {
        float S = 0.f, Q = 0.f;
#pragma unroll
        for (int k = 0; k < 8; k++) { S += shs[k]; Q += shq[k]; }
        g_red[c][n] = make_float2(S, Q);
        __threadfence();
        int old = atomicAdd(&g_cnt[layer * 64 + c], 1);
        if (old == 3) {
            __threadfence();
            volatile float* rp = (volatile float*)&g_red[c][0];
            float TS = 0.f, TQ = 0.f;
#pragma unroll
            for (int k = 0; k < 4; k++) { TS += rp[2 * k]; TQ += rp[2 * k + 1]; }
            float mean = TS * (1.f / 4096.f);
            float var = TQ * (1.f / 4096.f) - mean * mean;
            float a = gamma[c] * rsqrtf(var + EPSV);
            g_bn_a[c] = a;
            g_bn_b[c] = beta[c] - mean * a;
        }
    }
}

// ---------------- combine regressor partials + bias -> xf ----------------
template <int NPARTS>
__global__ void combine_xf_kernel(const float* __restrict__ reg_b) {
    cudaGridDependencySynchronize();
    int i = blockIdx.x * 256 + threadIdx.x;
    if (i < 4 * 12 * 1024) {
        int c = (i >> 10) % 12;
        float s = reg_b[c];
#pragma unroll
        for (int p = 0; p < NPARTS; p++) s += g_part[p][i];
        g_xf[i] = s;
    }
}

// ---------------- attention: block per (t,i); att_w row staged pre-sync in SMEM ----------------
__global__ __launch_bounds__(128) void attention3_kernel(const float* __restrict__ att_w,
                                                         float* __restrict__ out,
                                                         float* __restrict__ att) {
    const int ti = blockIdx.x;
    const int t = ti >> 10;
    const int tid = threadIdx.x;
    const int warp = tid >> 5;
    const int lane = tid & 31;
    const int nt = warp * 12 + t;

    __shared__ __align__(16) float4 sw[256];
    {
        const float4* wrow4 = (const float4*)(att_w + ((size_t)ti << 10));
        sw[tid] = __ldg(wrow4 + tid);
        sw[tid + 128] = __ldg(wrow4 + tid + 128);
    }

    cudaGridDependencySynchronize();

    const float4* xrow = ((const float4*)(g_xf + ((size_t)nt << 10))) + lane;
    float4 x[8];
#pragma unroll
    for (int k = 0; k < 8; k++) x[k] = __ldg(xrow + k * 32);

    __syncthreads();

    float4 s[8];
    float m = -3.0e38f;
#pragma unroll
    for (int k = 0; k < 8; k++) {
        float4 w = sw[lane + k * 32];
        s[k].x = w.x * x[k].x; s[k].y = w.y * x[k].y;
        s[k].z = w.z * x[k].z; s[k].w = w.w * x[k].w;
        m = fmaxf(m, fmaxf(fmaxf(s[k].x, s[k].y), fmaxf(s[k].z, s[k].w)));
    }
#pragma unroll
    for (int o = 16; o > 0; o >>= 1) m = fmaxf(m, __shfl_xor_sync(0xffffffffu, m, o));

    float es = 0.f, ed = 0.f;
#pragma unroll
    for (int k = 0; k < 8; k++) {
        float4 e;
        e.x = __expf(s[k].x - m); e.y = __expf(s[k].y - m);
        e.z = __expf(s[k].z - m); e.w = __expf(s[k].w - m);
        s[k] = e;
        es += e.x + e.y + e.z + e.w;
        ed += e.x * x[k].x + e.y * x[k].y + e.z * x[k].z + e.w * x[k].w;
    }
#pragma unroll
    for (int o = 16; o > 0; o >>= 1) {
        es += __shfl_xor_sync(0xffffffffu, es, o);
        ed += __shfl_xor_sync(0xffffffffu, ed, o);
    }

    const float inv = __frcp_rn(es);
    const size_t rid = ((size_t)nt << 10) + (ti & 1023);
    float4* dstrow = ((float4*)(att + (rid << 10))) + lane;
#pragma unroll
    for (int k = 0; k < 8; k++) {
        float4 o4 = make_float4(s[k].x * inv, s[k].y * inv, s[k].z * inv, s[k].w * inv);
        __stcs(dstrow + k * 32, o4);
    }
    if (lane == 0) out[rid] = ed * inv;
}

// ---------------- PDL launch helper ----------------
template <typename K, typename... Args>
static inline void launch_pdl(K kern, dim3 grid, dim3 block, Args... args) {
    cudaLaunchConfig_t cfg = {};
    cfg.gridDim = grid;
    cfg.blockDim = block;
    cfg.dynamicSmemBytes = 0;
    cfg.stream = 0;
    cudaLaunchAttribute attr[1];
    attr[0].id = cudaLaunchAttributeProgrammaticStreamSerialization;
    attr[0].val.programmaticStreamSerializationAllowed = 1;
    cfg.attrs = attr;
    cfg.numAttrs = 1;
    cudaLaunchKernelEx(&cfg, kern, args...);
}

// ---------------- launcher ----------------
extern "C" void kernel_launch(void* const* d_in, const int* in_sizes, int n_in,
                              void* d_out, int out_size) {
    (void)in_sizes; (void)n_in; (void)out_size;
    const float* x        = (const float*)d_in[0];
    const float* conv0_w  = (const float*)d_in[1];
    const float* conv_w   = (const float*)d_in[2];
    // d_in[3] = conv_b: zero and exactly cancelled by BN -> unused
    const float* bn_gamma = (const float*)d_in[4];
    const float* bn_beta  = (const float*)d_in[5];
    const float* reg_w    = (const float*)d_in[6];
    const float* reg_b    = (const float*)d_in[7];
    const float* att_w    = (const float*)d_in[8];
    float* out = (float*)d_out;

    float *p_y, *p_part, *p_wT;
    cudaGetSymbolAddress((void**)&p_y, g_y);
    cudaGetSymbolAddress((void**)&p_part, g_part);
    cudaGetSymbolAddress((void**)&p_wT, g_wT);

    wtrans_kernel<<<640, 256>>>(conv0_w, conv_w, reg_w);

    // layer 0: 12 -> 64, split-K x12 (CIQ=1) x co-split 2 = 768 blocks x 128 thr
    launch_pdl(convp_kernel<12, false, 12, true>, dim3(32, 24), dim3(128),
               x, (const float*)p_wT, p_part);
    launch_pdl(stats_kernel<12>, dim3(256), dim3(256), bn_gamma + 0, bn_beta + 0, 0);

    // layers 1..4: 64 -> 64, split-K x16 (CIQ=4) x co-split 2 = 1024 blocks x 128 thr
    launch_pdl(convp_kernel<64, true, 16, false>, dim3(32, 32), dim3(128),
               (const float*)p_y, (const float*)(p_wT + 6912 + 0 * 36864), p_part);
    launch_pdl(stats_kernel<16>, dim3(256), dim3(256), bn_gamma + 1 * 64, bn_beta + 1 * 64, 1);
    launch_pdl(convp_kernel<64, true, 16, false>, dim3(32, 32), dim3(128),
               (const float*)p_y, (const float*)(p_wT + 6912 + 1 * 36864), p_part);
    launch_pdl(stats_kernel<16>, dim3(256), dim3(256), bn_gamma + 2 * 64, bn_beta + 2 * 64, 2);
    launch_pdl(convp_kernel<64, true, 16, false>, dim3(32, 32), dim3(128),
               (const float*)p_y, (const float*)(p_wT + 6912 + 2 * 36864), p_part);
    launch_pdl(stats_kernel<16>, dim3(256), dim3(256), bn_gamma + 3 * 64, bn_beta + 3 * 64, 3);
    launch_pdl(convp_kernel<64, true, 16, false>, dim3(32, 32), dim3(128),
               (const float*)p_y, (const float*)(p_wT + 6912 + 3 * 36864), p_part);
    launch_pdl(stats_kernel<16>, dim3(256), dim3(256), bn_gamma + 4 * 64, bn_beta + 4 * 64, 4);

    // regressor: 64 -> 12 (padded to 16 co), 8-row tiles, split-K x8
    launch_pdl(convr_kernel<64, 16, 8, true, 12, 8>, dim3(16, 8), dim3(256),
               (const float*)p_y, (const float*)(p_wT + 154368), p_part);
    launch_pdl(combine_xf_kernel<8>, dim3(192), dim3(256), reg_b);

    // attention: out (49152 floats) then att (4*12*1024*1024)
    launch_pdl(attention3_kernel, dim3(12288), dim3(128), att_w, out, out + 49152);
}

// round 15
// speedup vs baseline: 1.0487x; 1.0487x over previous
#include <cuda_runtime.h>

typedef unsigned long long ull;
#define EPSV 1e-5f
#define SLICE (4 * 64 * 1024)

// ---------------- scratch (device globals) ----------------
__device__ float g_part[8][SLICE];           // split-K(<=8) partial conv outputs
__device__ float g_y[SLICE];                 // combined raw conv output (pre-BN)
__device__ float g_bn_a[64];                 // folded BN scale
__device__ float g_bn_b[64];                 // folded BN shift
__device__ float g_xf[4 * 12 * 1024];        // regressor output (N,T,WH)
__device__ float g_wT[163584];               // transposed weights [ci][tap][co]
__device__ float2 g_red[64][4];              // per-(channel, image) {sum, sumsq}
__device__ int g_cnt[5 * 64];                // last-block counters per layer/channel

// wT layout: L0 [12][9][64] @0 (6912); L1..4 [64][9][64] @6912+l*36864; reg [64][9][16] @154368

__device__ __forceinline__ void fma2(ull& acc, ull x, ull w) {
    asm("fma.rn.f32x2 %0, %1, %2, %0;" : "+l"(acc) : "l"(x), "l"(w));
}
__device__ __forceinline__ ull dup2(float v) {
    union { float2 f; ull u; } t;
    t.f = make_float2(v, v);
    return t.u;
}

// ---------------- weight transpose + counter reset ----------------
__global__ void wtrans_kernel(const float* __restrict__ conv0_w,
                              const float* __restrict__ conv_w,
                              const float* __restrict__ reg_w) {
    int i = blockIdx.x * 256 + threadIdx.x;
    if (i < 320) g_cnt[i] = 0;
    if (i < 6912) {
        int co = i & 63, rest = i >> 6;
        int tap = rest % 9, ci = rest / 9;
        g_wT[i] = conv0_w[co * 108 + ci * 9 + tap];
        return;
    }
    int j = i - 6912;
    if (j >= 0 && j < 147456) {
        int l = j / 36864, k = j % 36864;
        int co = k & 63, rest = k >> 6;
        int tap = rest % 9, ci = rest / 9;
        g_wT[i] = conv_w[(l * 64 + co) * 576 + ci * 9 + tap];
        return;
    }
    int r = i - 154368;
    if (r >= 0 && r < 9216) {
        int co = r & 15, rest = r >> 4;
        int tap = rest % 9, ci = rest / 9;
        g_wT[i] = (co < 12) ? reg_w[co * 576 + ci * 9 + tap] : 0.f;
    }
}

// ---------------- dense-pixel conv v2: 256 thr, warp = 4co, co-split x2 ----------------
// grid: (32 tiles, SPLITK*2): blockIdx.y>>1 = ci-split, blockIdx.y&1 = co half (32 co).
// smA: dense floats [CIQ][6][40], halos zero; smW: [CIQ][9][32].
template <int CI, bool BN, int SPLITK, bool ACTFIRST>
__global__ __launch_bounds__(256, 2) void convp2_kernel(const float* __restrict__ in,
                                                        const float* __restrict__ wT,
                                                        float* __restrict__ part) {
    constexpr int CIQ = CI / SPLITK;
    const int tid = threadIdx.x;
    const int warp = tid >> 5;               // 8 warps = 8 x 4co covering 32 co
    const int lane = tid & 31;
    const int coBase = (blockIdx.y & 1) * 32;
    const int row = lane >> 3;               // 0..3
    const int pc = (lane & 7) * 4;
    const int px0 = blockIdx.x * 128;        // 4 rows x 32 cols
    const int n = px0 >> 10;
    const int r0 = (px0 & 1023) >> 5;
    const int ci0 = (blockIdx.y >> 1) * CIQ;

    __shared__ __align__(16) float smA[CIQ][6][40];
    __shared__ __align__(16) float smW[CIQ][9][32];

    auto stageActs = [&]() {
        if (tid < CIQ * 12) {
            int pair = tid >> 1;
            int ci = pair / 6, rw = pair % 6;
            smA[ci][rw][(tid & 1) ? 33 : 0] = 0.f;
        }
        for (int idx = tid; idx < CIQ * 48; idx += 256) {
            int ci = idx / 48, rem = idx % 48;
            int rw = rem / 8, q = rem % 8;
            int gr = r0 - 1 + rw;
            int cig = ci0 + ci;
            float4 v = make_float4(0.f, 0.f, 0.f, 0.f);
            if ((unsigned)gr < 32u) {
                v = *(const float4*)&in[((n * CI + cig) << 10) + (gr << 5) + q * 4];
                if (BN) {
                    float a = g_bn_a[cig], b = g_bn_b[cig];
                    v.x = fmaxf(fmaf(v.x, a, b), 0.f);
                    v.y = fmaxf(fmaf(v.y, a, b), 0.f);
                    v.z = fmaxf(fmaf(v.z, a, b), 0.f);
                    v.w = fmaxf(fmaf(v.w, a, b), 0.f);
                }
            }
            float* d = &smA[ci][rw][1 + q * 4];
            d[0] = v.x; d[1] = v.y; d[2] = v.z; d[3] = v.w;
        }
    };
    auto stageWeights = [&]() {
        const float4* src = (const float4*)wT;
        float4* dstw = (float4*)&smW[0][0][0];
        for (int idx = tid; idx < CIQ * 72; idx += 256) {
            int ci = idx / 72, rem = idx % 72;
            int tap = rem / 8, q = rem % 8;
            dstw[idx] = src[((ci0 + ci) * 9 + tap) * 16 + (coBase >> 2) + q];
        }
    };

    if (ACTFIRST) {
        stageActs();
        cudaGridDependencySynchronize();
        stageWeights();
    } else {
        stageWeights();
        cudaGridDependencySynchronize();
        stageActs();
    }
    __syncthreads();

    // ---- compute: acc[jp][cp] = co-pair {4*warp+2cp, +1}, pixel (row, pc+jp) ----
    ull acc[4][2];
#pragma unroll
    for (int a = 0; a < 4; a++) { acc[a][0] = 0ULL; acc[a][1] = 0ULL; }

#pragma unroll
    for (int ci = 0; ci < CIQ; ci++) {
#pragma unroll
        for (int kh = 0; kh < 3; kh++) {
            const float* ar = &smA[ci][row + kh][pc];
            float4 a03 = *(const float4*)ar;
            float2 a45 = *(const float2*)(ar + 4);
            ull d[6];
            d[0] = dup2(a03.x); d[1] = dup2(a03.y);
            d[2] = dup2(a03.z); d[3] = dup2(a03.w);
            d[4] = dup2(a45.x); d[5] = dup2(a45.y);
#pragma unroll
            for (int kw = 0; kw < 3; kw++) {
                const float* wr = &smW[ci][kh * 3 + kw][warp * 4];
                ulonglong2 w01 = *(const ulonglong2*)wr;   // 4 co (broadcast)
#pragma unroll
                for (int jp = 0; jp < 4; jp++) {
                    ull xx = d[kw + jp];
                    fma2(acc[jp][0], xx, w01.x);
                    fma2(acc[jp][1], xx, w01.y);
                }
            }
        }
    }

    // ---- epilogue ----
    union U { ull u; float2 f; };
    float* dst = part + (blockIdx.y >> 1) * SLICE;
#pragma unroll
    for (int cp = 0; cp < 2; cp++) {
#pragma unroll
        for (int h = 0; h < 2; h++) {
            const int co = coBase + warp * 4 + cp * 2 + h;
            float4 o;
            { U u; u.u = acc[0][cp]; o.x = h ? u.f.y : u.f.x; }
            { U u; u.u = acc[1][cp]; o.y = h ? u.f.y : u.f.x; }
            { U u; u.u = acc[2][cp]; o.z = h ? u.f.y : u.f.x; }
            { U u; u.u = acc[3][cp]; o.w = h ? u.f.y : u.f.x; }
            *(float4*)&dst[((n * 64 + co) << 10) + ((r0 + row) << 5) + pc] = o;
        }
    }
}

// ---------------- duplicated-pixel staging (regressor conv) ----------------
template <int CI, int CIQ, int ROWS, bool BN, int NT>
__device__ __forceinline__ void stage_input(float2 (*smA)[ROWS + 2][36],
                                            const float* __restrict__ in,
                                            int tid, int n, int r0, int ci0) {
    constexpr int NR = ROWS + 2;
    constexpr int NPAIR = CIQ * NR;
    constexpr int NV = NPAIR * 8;
    if (tid < NPAIR * 2) {
        int pair = tid >> 1;
        int ci = pair / NR, row = pair % NR;
        smA[ci][row][(tid & 1) ? 33 : 0] = make_float2(0.f, 0.f);
    }
    for (int idx = tid; idx < NV; idx += NT) {
        int pair = idx >> 3, q = idx & 7;
        int ci = pair / NR, row = pair % NR;
        int gr = r0 - 1 + row;
        int cig = ci0 + ci;
        float4 v = make_float4(0.f, 0.f, 0.f, 0.f);
        if ((unsigned)gr < 32u) {
            v = *(const float4*)&in[((n * CI + cig) << 10) + (gr << 5) + q * 4];
            if (BN) {
                float a = g_bn_a[cig], b = g_bn_b[cig];
                v.x = fmaxf(fmaf(v.x, a, b), 0.f);
                v.y = fmaxf(fmaf(v.y, a, b), 0.f);
                v.z = fmaxf(fmaf(v.z, a, b), 0.f);
                v.w = fmaxf(fmaf(v.w, a, b), 0.f);
            }
        }
        float2* base = &smA[ci][row][1 + q * 4];
        base[0] = make_float2(v.x, v.x);
        base[1] = make_float2(v.y, v.y);
        base[2] = make_float2(v.z, v.z);
        base[3] = make_float2(v.w, v.w);
    }
}

// ---------------- regressor conv: 4px x 4co per thread ----------------
template <int CI, int CO, int ROWS, bool BN, int STORECO, int SPLITK>
__global__ __launch_bounds__(256, 1) void convr_kernel(const float* __restrict__ in,
                                                       const float* __restrict__ wT,
                                                       float* __restrict__ part) {
    constexpr int TCO = CO / 4;
    constexpr int CIQ = CI / SPLITK;
    const int tid = threadIdx.x;
    const int tco = tid % TCO;
    const int tpx = tid / TCO;
    const int pr = tpx >> 3;
    const int pc = (tpx & 7) * 4;
    const int px0 = blockIdx.x * (ROWS * 32);
    const int n = px0 >> 10;
    const int r0 = (px0 & 1023) >> 5;
    const int ci0 = blockIdx.y * CIQ;

    __shared__ __align__(16) float2 smA[CIQ][ROWS + 2][36];
    __shared__ __align__(16) float smW[CIQ][9][CO];

    {
        const float4* src = (const float4*)(wT + ci0 * 9 * CO);
        float4* dstw = (float4*)&smW[0][0][0];
        for (int idx = tid; idx < CIQ * 9 * CO / 4; idx += 256) dstw[idx] = src[idx];
    }
    cudaGridDependencySynchronize();
    stage_input<CI, CIQ, ROWS, BN, 256>(smA, in, tid, n, r0, ci0);
    __syncthreads();

    ull acc[4][2];
#pragma unroll
    for (int a = 0; a < 4; a++) { acc[a][0] = 0ULL; acc[a][1] = 0ULL; }

#pragma unroll
    for (int ci = 0; ci < CIQ; ci++) {
#pragma unroll
        for (int kh = 0; kh < 3; kh++) {
            ulonglong2 x01 = *(const ulonglong2*)&smA[ci][pr + kh][pc + 0];
            ulonglong2 x23 = *(const ulonglong2*)&smA[ci][pr + kh][pc + 2];
            ulonglong2 x45 = *(const ulonglong2*)&smA[ci][pr + kh][pc + 4];
            ull xp[6];
            xp[0] = x01.x; xp[1] = x01.y;
            xp[2] = x23.x; xp[3] = x23.y;
            xp[4] = x45.x; xp[5] = x45.y;
#pragma unroll
            for (int kw = 0; kw < 3; kw++) {
                ulonglong2 wv = *(const ulonglong2*)&smW[ci][kh * 3 + kw][tco * 4];
#pragma unroll
                for (int jp = 0; jp < 4; jp++) {
                    fma2(acc[jp][0], xp[kw + jp], wv.x);
                    fma2(acc[jp][1], xp[kw + jp], wv.y);
                }
            }
        }
    }

    union U { ull u; float2 f; };
    float vals[4][4];
#pragma unroll
    for (int jp = 0; jp < 4; jp++) {
        U u0, u1; u0.u = acc[jp][0]; u1.u = acc[jp][1];
        vals[jp][0] = u0.f.x; vals[jp][1] = u0.f.y;
        vals[jp][2] = u1.f.x; vals[jp][3] = u1.f.y;
    }
    float* dst = part + blockIdx.y * SLICE;
#pragma unroll
    for (int jc = 0; jc < 4; jc++) {
        int co = tco * 4 + jc;
        if (STORECO == CO || co < STORECO) {
            float4 o = make_float4(vals[0][jc], vals[1][jc], vals[2][jc], vals[3][jc]);
            *(float4*)&dst[((n * STORECO + co) << 10) + ((r0 + pr) << 5) + pc] = o;
        }
    }
}

// ---------------- combine partials -> y, BN stats, last-block folds (a,b) ----------------
template <int NPARTS>
__global__ __launch_bounds__(256) void stats_kernel(const float* __restrict__ gamma,
                                                    const float* __restrict__ beta,
                                                    int layer) {
    cudaGridDependencySynchronize();
    const int b = blockIdx.x;
    const int c = b & 63;
    const int n = b >> 6;
    const int tid = threadIdx.x;
    const int base = ((n * 64 + c) << 10) + tid * 4;

    float4 y = make_float4(0.f, 0.f, 0.f, 0.f);
#pragma unroll
    for (int p = 0; p < NPARTS; p++) {
        float4 v = *(const float4*)&g_part[p][base];
        y.x += v.x; y.y += v.y; y.z += v.z; y.w += v.w;
    }
    *(float4*)&g_y[base] = y;
    float s = y.x + y.y + y.z + y.w;
    float ss = y.x * y.x + y.y * y.y + y.z * y.z + y.w * y.w;

    const int lane = tid & 31, warp = tid >> 5;
#pragma unroll
    for (int o = 16; o > 0; o >>= 1) {
        s += __shfl_xor_sync(0xffffffffu, s, o);
        ss += __shfl_xor_sync(0xffffffffu, ss, o);
    }
    __shared__ float shs[8], shq[8];
    if (lane == 0) { shs[warp] = s; shq[warp] = ss; }
    __syncthreads();
    if (tid == 0) {
        float S = 0.f, Q = 0.f;
#pragma unroll
        for (int k = 0; k < 8; k++) { S += shs[k]; Q += shq[k]; }
        g_red[c][n] = make_float2(S, Q);
        __threadfence();
        int old = atomicAdd(&g_cnt[layer * 64 + c], 1);
        if (old == 3) {
            __threadfence();
            volatile float* rp = (volatile float*)&g_red[c][0];
            float TS = 0.f, TQ = 0.f;
#pragma unroll
            for (int k = 0; k < 4; k++) { TS += rp[2 * k]; TQ += rp[2 * k + 1]; }
            float mean = TS * (1.f / 4096.f);
            float var = TQ * (1.f / 4096.f) - mean * mean;
            float a = gamma[c] * rsqrtf(var + EPSV);
            g_bn_a[c] = a;
            g_bn_b[c] = beta[c] - mean * a;
        }
    }
}

// ---------------- combine regressor partials + bias -> xf ----------------
template <int NPARTS>
__global__ void combine_xf_kernel(const float* __restrict__ reg_b) {
    cudaGridDependencySynchronize();
    int i = blockIdx.x * 256 + threadIdx.x;
    if (i < 4 * 12 * 1024) {
        int c = (i >> 10) % 12;
        float s = reg_b[c];
#pragma unroll
        for (int p = 0; p < NPARTS; p++) s += g_part[p][i];
        g_xf[i] = s;
    }
}

// ---------------- attention: block per (t,i); att_w row staged pre-sync in SMEM ----------------
__global__ __launch_bounds__(128) void attention3_kernel(const float* __restrict__ att_w,
                                                         float* __restrict__ out,
                                                         float* __restrict__ att) {
    const int ti = blockIdx.x;
    const int t = ti >> 10;
    const int tid = threadIdx.x;
    const int warp = tid >> 5;
    const int lane = tid & 31;
    const int nt = warp * 12 + t;

    __shared__ __align__(16) float4 sw[256];
    {
        const float4* wrow4 = (const float4*)(att_w + ((size_t)ti << 10));
        sw[tid] = __ldg(wrow4 + tid);
        sw[tid + 128] = __ldg(wrow4 + tid + 128);
    }

    cudaGridDependencySynchronize();

    const float4* xrow = ((const float4*)(g_xf + ((size_t)nt << 10))) + lane;
    float4 x[8];
#pragma unroll
    for (int k = 0; k < 8; k++) x[k] = __ldg(xrow + k * 32);

    __syncthreads();

    float4 s[8];
    float m = -3.0e38f;
#pragma unroll
    for (int k = 0; k < 8; k++) {
        float4 w = sw[lane + k * 32];
        s[k].x = w.x * x[k].x; s[k].y = w.y * x[k].y;
        s[k].z = w.z * x[k].z; s[k].w = w.w * x[k].w;
        m = fmaxf(m, fmaxf(fmaxf(s[k].x, s[k].y), fmaxf(s[k].z, s[k].w)));
    }
#pragma unroll
    for (int o = 16; o > 0; o >>= 1) m = fmaxf(m, __shfl_xor_sync(0xffffffffu, m, o));

    float es = 0.f, ed = 0.f;
#pragma unroll
    for (int k = 0; k < 8; k++) {
        float4 e;
        e.x = __expf(s[k].x - m); e.y = __expf(s[k].y - m);
        e.z = __expf(s[k].z - m); e.w = __expf(s[k].w - m);
        s[k] = e;
        es += e.x + e.y + e.z + e.w;
        ed += e.x * x[k].x + e.y * x[k].y + e.z * x[k].z + e.w * x[k].w;
    }
#pragma unroll
    for (int o = 16; o > 0; o >>= 1) {
        es += __shfl_xor_sync(0xffffffffu, es, o);
        ed += __shfl_xor_sync(0xffffffffu, ed, o);
    }

    const float inv = __frcp_rn(es);
    const size_t rid = ((size_t)nt << 10) + (ti & 1023);
    float4* dstrow = ((float4*)(att + (rid << 10))) + lane;
#pragma unroll
    for (int k = 0; k < 8; k++) {
        float4 o4 = make_float4(s[k].x * inv, s[k].y * inv, s[k].z * inv, s[k].w * inv);
        __stcs(dstrow + k * 32, o4);
    }
    if (lane == 0) out[rid] = ed * inv;
}

// ---------------- PDL launch helper ----------------
template <typename K, typename... Args>
static inline void launch_pdl(K kern, dim3 grid, dim3 block, Args... args) {
    cudaLaunchConfig_t cfg = {};
    cfg.gridDim = grid;
    cfg.blockDim = block;
    cfg.dynamicSmemBytes = 0;
    cfg.stream = 0;
    cudaLaunchAttribute attr[1];
    attr[0].id = cudaLaunchAttributeProgrammaticStreamSerialization;
    attr[0].val.programmaticStreamSerializationAllowed = 1;
    cfg.attrs = attr;
    cfg.numAttrs = 1;
    cudaLaunchKernelEx(&cfg, kern, args...);
}

// ---------------- launcher ----------------
extern "C" void kernel_launch(void* const* d_in, const int* in_sizes, int n_in,
                              void* d_out, int out_size) {
    (void)in_sizes; (void)n_in; (void)out_size;
    const float* x        = (const float*)d_in[0];
    const float* conv0_w  = (const float*)d_in[1];
    const float* conv_w   = (const float*)d_in[2];
    // d_in[3] = conv_b: zero and exactly cancelled by BN -> unused
    const float* bn_gamma = (const float*)d_in[4];
    const float* bn_beta  = (const float*)d_in[5];
    const float* reg_w    = (const float*)d_in[6];
    const float* reg_b    = (const float*)d_in[7];
    const float* att_w    = (const float*)d_in[8];
    float* out = (float*)d_out;

    float *p_y, *p_part, *p_wT;
    cudaGetSymbolAddress((void**)&p_y, g_y);
    cudaGetSymbolAddress((void**)&p_part, g_part);
    cudaGetSymbolAddress((void**)&p_wT, g_wT);

    wtrans_kernel<<<640, 256>>>(conv0_w, conv_w, reg_w);

    // layer 0: 12 -> 64, split-K x4 (CIQ=3) x co-split 2 = 256 blocks x 256 thr
    launch_pdl(convp2_kernel<12, false, 4, true>, dim3(32, 8), dim3(256),
               x, (const float*)p_wT, p_part);
    launch_pdl(stats_kernel<4>, dim3(256), dim3(256), bn_gamma + 0, bn_beta + 0, 0);

    // layers 1..4: 64 -> 64, split-K x8 (CIQ=8) x co-split 2 = 512 blocks x 256 thr
    launch_pdl(convp2_kernel<64, true, 8, false>, dim3(32, 16), dim3(256),
               (const float*)p_y, (const float*)(p_wT + 6912 + 0 * 36864), p_part);
    launch_pdl(stats_kernel<8>, dim3(256), dim3(256), bn_gamma + 1 * 64, bn_beta + 1 * 64, 1);
    launch_pdl(convp2_kernel<64, true, 8, false>, dim3(32, 16), dim3(256),
               (const float*)p_y, (const float*)(p_wT + 6912 + 1 * 36864), p_part);
    launch_pdl(stats_kernel<8>, dim3(256), dim3(256), bn_gamma + 2 * 64, bn_beta + 2 * 64, 2);
    launch_pdl(convp2_kernel<64, true, 8, false>, dim3(32, 16), dim3(256),
               (const float*)p_y, (const float*)(p_wT + 6912 + 2 * 36864), p_part);
    launch_pdl(stats_kernel<8>, dim3(256), dim3(256), bn_gamma + 3 * 64, bn_beta + 3 * 64, 3);
    launch_pdl(convp2_kernel<64, true, 8, false>, dim3(32, 16), dim3(256),
               (const float*)p_y, (const float*)(p_wT + 6912 + 3 * 36864), p_part);
    launch_pdl(stats_kernel<8>, dim3(256), dim3(256), bn_gamma + 4 * 64, bn_beta + 4 * 64, 4);

    // regressor: 64 -> 12 (padded to 16 co), 8-row tiles, split-K x8
    launch_pdl(convr_kernel<64, 16, 8, true, 12, 8>, dim3(16, 8), dim3(256),
               (const float*)p_y, (const float*)(p_wT + 154368), p_part);
    launch_pdl(combine_xf_kernel<8>, dim3(192), dim3(256), reg_b);

    // attention: out (49152 floats) then att (4*12*1024*1024)
    launch_pdl(attention3_kernel, dim3(12288), dim3(128), att_w, out, out + 49152);
}

// round 16
// speedup vs baseline: 1.0588x; 1.0096x over previous
#include <cuda_runtime.h>

typedef unsigned long long ull;
#define EPSV 1e-5f
#define SLICE (4 * 64 * 1024)

// ---------------- scratch (device globals) ----------------
__device__ float g_part[8][SLICE];           // split-K(<=8) partial conv outputs
__device__ float g_y[SLICE];                 // combined raw conv output (pre-BN)
__device__ float g_bn_a[64];                 // folded BN scale
__device__ float g_bn_b[64];                 // folded BN shift
__device__ float g_xf[4 * 12 * 1024];        // regressor output (N,T,WH)
__device__ float g_wT[163584];               // transposed weights [ci][tap][co]
__device__ float2 g_red[64][4];              // per-(channel, image) {sum, sumsq}
__device__ int g_cnt[5 * 64];                // last-block counters per layer/channel

// wT layout: L0 [12][9][64] @0 (6912); L1..4 [64][9][64] @6912+l*36864; reg [64][9][16] @154368

__device__ __forceinline__ void fma2(ull& acc, ull x, ull w) {
    asm("fma.rn.f32x2 %0, %1, %2, %0;" : "+l"(acc) : "l"(x), "l"(w));
}
__device__ __forceinline__ ull dup2(float v) {
    union { float2 f; ull u; } t;
    t.f = make_float2(v, v);
    return t.u;
}

// ---------------- weight transpose + counter reset ----------------
__global__ void wtrans_kernel(const float* __restrict__ conv0_w,
                              const float* __restrict__ conv_w,
                              const float* __restrict__ reg_w) {
    int i = blockIdx.x * 256 + threadIdx.x;
    if (i < 320) g_cnt[i] = 0;
    if (i < 6912) {
        int co = i & 63, rest = i >> 6;
        int tap = rest % 9, ci = rest / 9;
        g_wT[i] = conv0_w[co * 108 + ci * 9 + tap];
        return;
    }
    int j = i - 6912;
    if (j >= 0 && j < 147456) {
        int l = j / 36864, k = j % 36864;
        int co = k & 63, rest = k >> 6;
        int tap = rest % 9, ci = rest / 9;
        g_wT[i] = conv_w[(l * 64 + co) * 576 + ci * 9 + tap];
        return;
    }
    int r = i - 154368;
    if (r >= 0 && r < 9216) {
        int co = r & 15, rest = r >> 4;
        int tap = rest % 9, ci = rest / 9;
        g_wT[i] = (co < 12) ? reg_w[co * 576 + ci * 9 + tap] : 0.f;
    }
}

// ---------------- dense-pixel conv v3: 256 thr, warp = 4co, co-split x2, batched loads ----------------
// grid: (32 tiles, SPLITK*2): blockIdx.y>>1 = ci-split, blockIdx.y&1 = co half (32 co).
// smA: dense floats [CIQ][6][40], halos zero; smW: [CIQ][9][32].
template <int CI, bool BN, int SPLITK, bool ACTFIRST>
__global__ __launch_bounds__(256) void convp3_kernel(const float* __restrict__ in,
                                                     const float* __restrict__ wT,
                                                     float* __restrict__ part) {
    constexpr int CIQ = CI / SPLITK;
    const int tid = threadIdx.x;
    const int warp = tid >> 5;               // 8 warps = 8 x 4co covering 32 co
    const int lane = tid & 31;
    const int coBase = (blockIdx.y & 1) * 32;
    const int row = lane >> 3;               // 0..3
    const int pc = (lane & 7) * 4;
    const int px0 = blockIdx.x * 128;        // 4 rows x 32 cols
    const int n = px0 >> 10;
    const int r0 = (px0 & 1023) >> 5;
    const int ci0 = (blockIdx.y >> 1) * CIQ;

    __shared__ __align__(16) float smA[CIQ][6][40];
    __shared__ __align__(16) float smW[CIQ][9][32];

    auto stageActs = [&]() {
        if (tid < CIQ * 12) {
            int pair = tid >> 1;
            int ci = pair / 6, rw = pair % 6;
            smA[ci][rw][(tid & 1) ? 33 : 0] = 0.f;
        }
        for (int idx = tid; idx < CIQ * 48; idx += 256) {
            int ci = idx / 48, rem = idx % 48;
            int rw = rem / 8, q = rem % 8;
            int gr = r0 - 1 + rw;
            int cig = ci0 + ci;
            float4 v = make_float4(0.f, 0.f, 0.f, 0.f);
            if ((unsigned)gr < 32u) {
                v = *(const float4*)&in[((n * CI + cig) << 10) + (gr << 5) + q * 4];
                if (BN) {
                    float a = g_bn_a[cig], b = g_bn_b[cig];
                    v.x = fmaxf(fmaf(v.x, a, b), 0.f);
                    v.y = fmaxf(fmaf(v.y, a, b), 0.f);
                    v.z = fmaxf(fmaf(v.z, a, b), 0.f);
                    v.w = fmaxf(fmaf(v.w, a, b), 0.f);
                }
            }
            float* d = &smA[ci][rw][1 + q * 4];
            d[0] = v.x; d[1] = v.y; d[2] = v.z; d[3] = v.w;
        }
    };
    auto stageWeights = [&]() {
        const float4* src = (const float4*)wT;
        float4* dstw = (float4*)&smW[0][0][0];
        for (int idx = tid; idx < CIQ * 72; idx += 256) {
            int ci = idx / 72, rem = idx % 72;
            int tap = rem / 8, q = rem % 8;
            dstw[idx] = src[((ci0 + ci) * 9 + tap) * 16 + (coBase >> 2) + q];
        }
    };

    if (ACTFIRST) {
        stageActs();
        cudaGridDependencySynchronize();
        stageWeights();
    } else {
        stageWeights();
        cudaGridDependencySynchronize();
        stageActs();
    }
    __syncthreads();

    // ---- compute: acc[jp][cp] = co-pair {4*warp+2cp, +1}, pixel (row, pc+jp) ----
    ull acc[4][2];
#pragma unroll
    for (int a = 0; a < 4; a++) { acc[a][0] = 0ULL; acc[a][1] = 0ULL; }

#pragma unroll
    for (int ci = 0; ci < CIQ; ci++) {
        // batched: issue all 6 activation LDS for the 3 kh rows back-to-back
        float4 a03[3];
        float2 a45[3];
#pragma unroll
        for (int kh = 0; kh < 3; kh++) {
            const float* ar = &smA[ci][row + kh][pc];
            a03[kh] = *(const float4*)ar;
            a45[kh] = *(const float2*)(ar + 4);
        }
#pragma unroll
        for (int kh = 0; kh < 3; kh++) {
            // batched: all 3 weight vectors for this kh
            ulonglong2 w0 = *(const ulonglong2*)&smW[ci][kh * 3 + 0][warp * 4];
            ulonglong2 w1 = *(const ulonglong2*)&smW[ci][kh * 3 + 1][warp * 4];
            ulonglong2 w2 = *(const ulonglong2*)&smW[ci][kh * 3 + 2][warp * 4];
            ull d[6];
            d[0] = dup2(a03[kh].x); d[1] = dup2(a03[kh].y);
            d[2] = dup2(a03[kh].z); d[3] = dup2(a03[kh].w);
            d[4] = dup2(a45[kh].x); d[5] = dup2(a45[kh].y);
#pragma unroll
            for (int jp = 0; jp < 4; jp++) {
                fma2(acc[jp][0], d[jp + 0], w0.x);
                fma2(acc[jp][1], d[jp + 0], w0.y);
                fma2(acc[jp][0], d[jp + 1], w1.x);
                fma2(acc[jp][1], d[jp + 1], w1.y);
                fma2(acc[jp][0], d[jp + 2], w2.x);
                fma2(acc[jp][1], d[jp + 2], w2.y);
            }
        }
    }

    // ---- epilogue ----
    union U { ull u; float2 f; };
    float* dst = part + (blockIdx.y >> 1) * SLICE;
#pragma unroll
    for (int cp = 0; cp < 2; cp++) {
#pragma unroll
        for (int h = 0; h < 2; h++) {
            const int co = coBase + warp * 4 + cp * 2 + h;
            float4 o;
            { U u; u.u = acc[0][cp]; o.x = h ? u.f.y : u.f.x; }
            { U u; u.u = acc[1][cp]; o.y = h ? u.f.y : u.f.x; }
            { U u; u.u = acc[2][cp]; o.z = h ? u.f.y : u.f.x; }
            { U u; u.u = acc[3][cp]; o.w = h ? u.f.y : u.f.x; }
            *(float4*)&dst[((n * 64 + co) << 10) + ((r0 + row) << 5) + pc] = o;
        }
    }
}

// ---------------- duplicated-pixel staging (regressor conv) ----------------
template <int CI, int CIQ, int ROWS, bool BN, int NT>
__device__ __forceinline__ void stage_input(float2 (*smA)[ROWS + 2][36],
                                            const float* __restrict__ in,
                                            int tid, int n, int r0, int ci0) {
    constexpr int NR = ROWS + 2;
    constexpr int NPAIR = CIQ * NR;
    constexpr int NV = NPAIR * 8;
    if (tid < NPAIR * 2) {
        int pair = tid >> 1;
        int ci = pair / NR, row = pair % NR;
        smA[ci][row][(tid & 1) ? 33 : 0] = make_float2(0.f, 0.f);
    }
    for (int idx = tid; idx < NV; idx += NT) {
        int pair = idx >> 3, q = idx & 7;
        int ci = pair / NR, row = pair % NR;
        int gr = r0 - 1 + row;
        int cig = ci0 + ci;
        float4 v = make_float4(0.f, 0.f, 0.f, 0.f);
        if ((unsigned)gr < 32u) {
            v = *(const float4*)&in[((n * CI + cig) << 10) + (gr << 5) + q * 4];
            if (BN) {
                float a = g_bn_a[cig], b = g_bn_b[cig];
                v.x = fmaxf(fmaf(v.x, a, b), 0.f);
                v.y = fmaxf(fmaf(v.y, a, b), 0.f);
                v.z = fmaxf(fmaf(v.z, a, b), 0.f);
                v.w = fmaxf(fmaf(v.w, a, b), 0.f);
            }
        }
        float2* base = &smA[ci][row][1 + q * 4];
        base[0] = make_float2(v.x, v.x);
        base[1] = make_float2(v.y, v.y);
        base[2] = make_float2(v.z, v.z);
        base[3] = make_float2(v.w, v.w);
    }
}

// ---------------- regressor conv: 4px x 4co per thread ----------------
template <int CI, int CO, int ROWS, bool BN, int STORECO, int SPLITK>
__global__ __launch_bounds__(256, 1) void convr_kernel(const float* __restrict__ in,
                                                       const float* __restrict__ wT,
                                                       float* __restrict__ part) {
    constexpr int TCO = CO / 4;
    constexpr int CIQ = CI / SPLITK;
    const int tid = threadIdx.x;
    const int tco = tid % TCO;
    const int tpx = tid / TCO;
    const int pr = tpx >> 3;
    const int pc = (tpx & 7) * 4;
    const int px0 = blockIdx.x * (ROWS * 32);
    const int n = px0 >> 10;
    const int r0 = (px0 & 1023) >> 5;
    const int ci0 = blockIdx.y * CIQ;

    __shared__ __align__(16) float2 smA[CIQ][ROWS + 2][36];
    __shared__ __align__(16) float smW[CIQ][9][CO];

    {
        const float4* src = (const float4*)(wT + ci0 * 9 * CO);
        float4* dstw = (float4*)&smW[0][0][0];
        for (int idx = tid; idx < CIQ * 9 * CO / 4; idx += 256) dstw[idx] = src[idx];
    }
    cudaGridDependencySynchronize();
    stage_input<CI, CIQ, ROWS, BN, 256>(smA, in, tid, n, r0, ci0);
    __syncthreads();

    ull acc[4][2];
#pragma unroll
    for (int a = 0; a < 4; a++) { acc[a][0] = 0ULL; acc[a][1] = 0ULL; }

#pragma unroll
    for (int ci = 0; ci < CIQ; ci++) {
#pragma unroll
        for (int kh = 0; kh < 3; kh++) {
            ulonglong2 x01 = *(const ulonglong2*)&smA[ci][pr + kh][pc + 0];
            ulonglong2 x23 = *(const ulonglong2*)&smA[ci][pr + kh][pc + 2];
            ulonglong2 x45 = *(const ulonglong2*)&smA[ci][pr + kh][pc + 4];
            ull xp[6];
            xp[0] = x01.x; xp[1] = x01.y;
            xp[2] = x23.x; xp[3] = x23.y;
            xp[4] = x45.x; xp[5] = x45.y;
#pragma unroll
            for (int kw = 0; kw < 3; kw++) {
                ulonglong2 wv = *(const ulonglong2*)&smW[ci][kh * 3 + kw][tco * 4];
#pragma unroll
                for (int jp = 0; jp < 4; jp++) {
                    fma2(acc[jp][0], xp[kw + jp], wv.x);
                    fma2(acc[jp][1], xp[kw + jp], wv.y);
                }
            }
        }
    }

    union U { ull u; float2 f; };
    float vals[4][4];
#pragma unroll
    for (int jp = 0; jp < 4; jp++) {
        U u0, u1; u0.u = acc[jp][0]; u1.u = acc[jp][1];
        vals[jp][0] = u0.f.x; vals[jp][1] = u0.f.y;
        vals[jp][2] = u1.f.x; vals[jp][3] = u1.f.y;
    }
    float* dst = part + blockIdx.y * SLICE;
#pragma unroll
    for (int jc = 0; jc < 4; jc++) {
        int co = tco * 4 + jc;
        if (STORECO == CO || co < STORECO) {
            float4 o = make_float4(vals[0][jc], vals[1][jc], vals[2][jc], vals[3][jc]);
            *(float4*)&dst[((n * STORECO + co) << 10) + ((r0 + pr) << 5) + pc] = o;
        }
    }
}

// ---------------- combine partials -> y, BN stats, last-block folds (a,b) ----------------
template <int NPARTS>
__global__ __launch_bounds__(256) void stats_kernel(const float* __restrict__ gamma,
                                                    const float* __restrict__ beta,
                                                    int layer) {
    cudaGridDependencySynchronize();
    const int b = blockIdx.x;
    const int c = b & 63;
    const int n = b >> 6;
    const int tid = threadIdx.x;
    const int base = ((n * 64 + c) << 10) + tid * 4;

    float4 y = make_float4(0.f, 0.f, 0.f, 0.f);
#pragma unroll
    for (int p = 0; p < NPARTS; p++) {
        float4 v = *(const float4*)&g_part[p][base];
        y.x += v.x; y.y += v.y; y.z += v.z; y.w += v.w;
    }
    *(float4*)&g_y[base] = y;
    float s = y.x + y.y + y.z + y.w;
    float ss = y.x * y.x + y.y * y.y + y.z * y.z + y.w * y.w;

    const int lane = tid & 31, warp = tid >> 5;
#pragma unroll
    for (int o = 16; o > 0; o >>= 1) {
        s += __shfl_xor_sync(0xffffffffu, s, o);
        ss += __shfl_xor_sync(0xffffffffu, ss, o);
    }
    __shared__ float shs[8], shq[8];
    if (lane == 0) { shs[warp] = s; shq[warp] = ss; }
    __syncthreads();
    if (tid == 0) {
        float S = 0.f, Q = 0.f;
#pragma unroll
        for (int k = 0; k < 8; k++) { S += shs[k]; Q += shq[k]; }
        g_red[c][n] = make_float2(S, Q);
        __threadfence();
        int old = atomicAdd(&g_cnt[layer * 64 + c], 1);
        if (old == 3) {
            __threadfence();
            volatile float* rp = (volatile float*)&g_red[c][0];
            float TS = 0.f, TQ = 0.f;
#pragma unroll
            for (int k = 0; k < 4; k++) { TS += rp[2 * k]; TQ += rp[2 * k + 1]; }
            float mean = TS * (1.f / 4096.f);
            float var = TQ * (1.f / 4096.f) - mean * mean;
            float a = gamma[c] * rsqrtf(var + EPSV);
            g_bn_a[c] = a;
            g_bn_b[c] = beta[c] - mean * a;
        }
    }
}

// ---------------- combine regressor partials + bias -> xf ----------------
template <int NPARTS>
__global__ void combine_xf_kernel(const float* __restrict__ reg_b) {
    cudaGridDependencySynchronize();
    int i = blockIdx.x * 256 + threadIdx.x;
    if (i < 4 * 12 * 1024) {
        int c = (i >> 10) % 12;
        float s = reg_b[c];
#pragma unroll
        for (int p = 0; p < NPARTS; p++) s += g_part[p][i];
        g_xf[i] = s;
    }
}

// ---------------- attention: block per (t,i); att_w row staged pre-sync in SMEM ----------------
__global__ __launch_bounds__(128) void attention3_kernel(const float* __restrict__ att_w,
                                                         float* __restrict__ out,
                                                         float* __restrict__ att) {
    const int ti = blockIdx.x;
    const int t = ti >> 10;
    const int tid = threadIdx.x;
    const int warp = tid >> 5;
    const int lane = tid & 31;
    const int nt = warp * 12 + t;

    __shared__ __align__(16) float4 sw[256];
    {
        const float4* wrow4 = (const float4*)(att_w + ((size_t)ti << 10));
        sw[tid] = __ldg(wrow4 + tid);
        sw[tid + 128] = __ldg(wrow4 + tid + 128);
    }

    cudaGridDependencySynchronize();

    const float4* xrow = ((const float4*)(g_xf + ((size_t)nt << 10))) + lane;
    float4 x[8];
#pragma unroll
    for (int k = 0; k < 8; k++) x[k] = __ldg(xrow + k * 32);

    __syncthreads();

    float4 s[8];
    float m = -3.0e38f;
#pragma unroll
    for (int k = 0; k < 8; k++) {
        float4 w = sw[lane + k * 32];
        s[k].x = w.x * x[k].x; s[k].y = w.y * x[k].y;
        s[k].z = w.z * x[k].z; s[k].w = w.w * x[k].w;
        m = fmaxf(m, fmaxf(fmaxf(s[k].x, s[k].y), fmaxf(s[k].z, s[k].w)));
    }
#pragma unroll
    for (int o = 16; o > 0; o >>= 1) m = fmaxf(m, __shfl_xor_sync(0xffffffffu, m, o));

    float es = 0.f, ed = 0.f;
#pragma unroll
    for (int k = 0; k < 8; k++) {
        float4 e;
        e.x = __expf(s[k].x - m); e.y = __expf(s[k].y - m);
        e.z = __expf(s[k].z - m); e.w = __expf(s[k].w - m);
        s[k] = e;
        es += e.x + e.y + e.z + e.w;
        ed += e.x * x[k].x + e.y * x[k].y + e.z * x[k].z + e.w * x[k].w;
    }
#pragma unroll
    for (int o = 16; o > 0; o >>= 1) {
        es += __shfl_xor_sync(0xffffffffu, es, o);
        ed += __shfl_xor_sync(0xffffffffu, ed, o);
    }

    const float inv = __frcp_rn(es);
    const size_t rid = ((size_t)nt << 10) + (ti & 1023);
    float4* dstrow = ((float4*)(att + (rid << 10))) + lane;
#pragma unroll
    for (int k = 0; k < 8; k++) {
        float4 o4 = make_float4(s[k].x * inv, s[k].y * inv, s[k].z * inv, s[k].w * inv);
        __stcs(dstrow + k * 32, o4);
    }
    if (lane == 0) out[rid] = ed * inv;
}

// ---------------- PDL launch helper ----------------
template <typename K, typename... Args>
static inline void launch_pdl(K kern, dim3 grid, dim3 block, Args... args) {
    cudaLaunchConfig_t cfg = {};
    cfg.gridDim = grid;
    cfg.blockDim = block;
    cfg.dynamicSmemBytes = 0;
    cfg.stream = 0;
    cudaLaunchAttribute attr[1];
    attr[0].id = cudaLaunchAttributeProgrammaticStreamSerialization;
    attr[0].val.programmaticStreamSerializationAllowed = 1;
    cfg.attrs = attr;
    cfg.numAttrs = 1;
    cudaLaunchKernelEx(&cfg, kern, args...);
}

// ---------------- launcher ----------------
extern "C" void kernel_launch(void* const* d_in, const int* in_sizes, int n_in,
                              void* d_out, int out_size) {
    (void)in_sizes; (void)n_in; (void)out_size;
    const float* x        = (const float*)d_in[0];
    const float* conv0_w  = (const float*)d_in[1];
    const float* conv_w   = (const float*)d_in[2];
    // d_in[3] = conv_b: zero and exactly cancelled by BN -> unused
    const float* bn_gamma = (const float*)d_in[4];
    const float* bn_beta  = (const float*)d_in[5];
    const float* reg_w    = (const float*)d_in[6];
    const float* reg_b    = (const float*)d_in[7];
    const float* att_w    = (const float*)d_in[8];
    float* out = (float*)d_out;

    float *p_y, *p_part, *p_wT;
    cudaGetSymbolAddress((void**)&p_y, g_y);
    cudaGetSymbolAddress((void**)&p_part, g_part);
    cudaGetSymbolAddress((void**)&p_wT, g_wT);

    wtrans_kernel<<<640, 256>>>(conv0_w, conv_w, reg_w);

    // layer 0: 12 -> 64, split-K x4 (CIQ=3) x co-split 2 = 256 blocks x 256 thr
    launch_pdl(convp3_kernel<12, false, 4, true>, dim3(32, 8), dim3(256),
               x, (const float*)p_wT, p_part);
    launch_pdl(stats_kernel<4>, dim3(256), dim3(256), bn_gamma + 0, bn_beta + 0, 0);

    // layers 1..4: 64 -> 64, split-K x8 (CIQ=8) x co-split 2 = 512 blocks x 256 thr
    launch_pdl(convp3_kernel<64, true, 8, false>, dim3(32, 16), dim3(256),
               (const float*)p_y, (const float*)(p_wT + 6912 + 0 * 36864), p_part);
    launch_pdl(stats_kernel<8>, dim3(256), dim3(256), bn_gamma + 1 * 64, bn_beta + 1 * 64, 1);
    launch_pdl(convp3_kernel<64, true, 8, false>, dim3(32, 16), dim3(256),
               (const float*)p_y, (const float*)(p_wT + 6912 + 1 * 36864), p_part);
    launch_pdl(stats_kernel<8>, dim3(256), dim3(256), bn_gamma + 2 * 64, bn_beta + 2 * 64, 2);
    launch_pdl(convp3_kernel<64, true, 8, false>, dim3(32, 16), dim3(256),
               (const float*)p_y, (const float*)(p_wT + 6912 + 2 * 36864), p_part);
    launch_pdl(stats_kernel<8>, dim3(256), dim3(256), bn_gamma + 3 * 64, bn_beta + 3 * 64, 3);
    launch_pdl(convp3_kernel<64, true, 8, false>, dim3(32, 16), dim3(256),
               (const float*)p_y, (const float*)(p_wT + 6912 + 3 * 36864), p_part);
    launch_pdl(stats_kernel<8>, dim3(256), dim3(256), bn_gamma + 4 * 64, bn_beta + 4 * 64, 4);

    // regressor: 64 -> 12 (padded to 16 co), 8-row tiles, split-K x8
    launch_pdl(convr_kernel<64, 16, 8, true, 12, 8>, dim3(16, 8), dim3(256),
               (const float*)p_y, (const float*)(p_wT + 154368), p_part);
    launch_pdl(combine_xf_kernel<8>, dim3(192), dim3(256), reg_b);

    // attention: out (49152 floats) then att (4*12*1024*1024)
    launch_pdl(attention3_kernel, dim3(12288), dim3(128), att_w, out, out + 49152);
}